// round 1
// baseline (speedup 1.0000x reference)
#include <cuda_runtime.h>

// SNRContrastiveLoss: N=8192, D=256, NUM_CLASSES=512
// loss = pos_sum/pos_cnt + neg_sum/neg_cnt + 0.1*mean(|row_sum(e)|)
// distmat_ij = (s_i + s_j - 2*g_ij - (m_i-m_j)^2) / (s_i - m_i^2)   (corr cancels)

#define NROWS 8192
#define DDIM  256
#define BM 128
#define BN 128
#define BK 16
#define TM 8
#define TN 8

#define POS_MARGIN 0.01f
#define NEG_MARGIN 0.2f

__device__ float  g_e[NROWS * DDIM];   // normalized embeddings (8 MB)
__device__ float  g_s[NROWS];
__device__ float  g_m[NROWS];
__device__ float  g_iv[NROWS];
__device__ int    g_lab[NROWS];
__device__ double g_acc[5];            // pos_sum, pos_cnt, neg_sum, neg_cnt, reg_sum
__device__ int    g_is64;

__device__ __forceinline__ float warpSumF(float v) {
    #pragma unroll
    for (int o = 16; o > 0; o >>= 1) v += __shfl_xor_sync(0xffffffffu, v, o);
    return v;
}
__device__ __forceinline__ int warpSumI(int v) {
    #pragma unroll
    for (int o = 16; o > 0; o >>= 1) v += __shfl_xor_sync(0xffffffffu, v, o);
    return v;
}

// ---------------------------------------------------------------------------
// Kernel 0: zero accumulators + detect whether labels buffer is int64 or int32.
// If labels are int64 (little-endian, values 0..511), every odd 32-bit word in
// the first 8192 words is 0. For genuine int32 labels that is astronomically
// unlikely (p ~ (1/512)^4096).
// ---------------------------------------------------------------------------
__global__ void k_init(const int* __restrict__ lab32) {
    __shared__ int nz;
    int t = threadIdx.x;
    if (t == 0) nz = 0;
    __syncthreads();
    int loc = 0;
    for (int i = 2 * t + 1; i < NROWS; i += 2 * blockDim.x) loc |= lab32[i];
    if (loc) atomicOr(&nz, 1);
    __syncthreads();
    if (t == 0) {
        g_is64 = (nz == 0) ? 1 : 0;
        #pragma unroll
        for (int j = 0; j < 5; j++) g_acc[j] = 0.0;
    }
}

// ---------------------------------------------------------------------------
// Kernel 1: per-row normalize + stats. One block (256 threads) per row.
// ---------------------------------------------------------------------------
__global__ __launch_bounds__(256) void k_prep(const float* __restrict__ x,
                                              const int* __restrict__ lab32) {
    int row = blockIdx.x;
    int t = threadIdx.x;
    float v = x[row * DDIM + t];

    __shared__ float sh[8];
    float s2 = warpSumF(v * v);
    if ((t & 31) == 0) sh[t >> 5] = s2;
    __syncthreads();
    if (t < 32) {
        float z = (t < 8) ? sh[t] : 0.0f;
        z = warpSumF(z);
        if (t == 0) sh[0] = z;
    }
    __syncthreads();
    float rinv = rsqrtf(sh[0]);
    float e = v * rinv;
    g_e[row * DDIM + t] = e;
    __syncthreads();

    __shared__ float she[8], she2[8];
    float re = warpSumF(e);
    float re2 = warpSumF(e * e);
    if ((t & 31) == 0) { she[t >> 5] = re; she2[t >> 5] = re2; }
    __syncthreads();
    if (t == 0) {
        float se = 0.0f, se2 = 0.0f;
        #pragma unroll
        for (int i = 0; i < 8; i++) { se += she[i]; se2 += she2[i]; }
        float m = se * (1.0f / DDIM);
        float s = se2 * (1.0f / DDIM);
        g_s[row] = s;
        g_m[row] = m;
        g_iv[row] = 1.0f / (s - m * m);
        g_lab[row] = g_is64 ? lab32[2 * row] : lab32[row];
        atomicAdd(&g_acc[4], (double)fabsf(se));
    }
}

// ---------------------------------------------------------------------------
// Kernel 2: fused pairwise tile kernel. Upper-triangular block tiles only;
// off-diagonal tiles apply the epilogue in both orientations (numerator is
// symmetric, only the 1/row_var_i divisor flips).
// ---------------------------------------------------------------------------
__global__ __launch_bounds__(256) void k_main() {
    int bi = blockIdx.y;
    int bj = blockIdx.x;
    if (bj < bi) return;

    __shared__ float As[BK][BM + 4];
    __shared__ float Bs[BK][BN + 4];

    int tid = threadIdx.x;
    int tx = tid & 15;       // 0..15 -> N
    int ty = tid >> 4;       // 0..15 -> M
    int m0 = ty * TM;
    int n0 = tx * TN;

    const float* Abase = g_e + (size_t)bi * BM * DDIM;
    const float* Bbase = g_e + (size_t)bj * BM * DDIM;

    float acc[TM][TN];
    #pragma unroll
    for (int i = 0; i < TM; i++)
        #pragma unroll
        for (int j = 0; j < TN; j++) acc[i][j] = 0.0f;

    for (int k0 = 0; k0 < DDIM; k0 += BK) {
        // load 128x16 fp32 tiles (2 float4 per thread per tile), transposed store
        #pragma unroll
        for (int l = 0; l < 2; l++) {
            int f = tid + l * 256;       // 0..511
            int r = f >> 2;              // row within tile
            int kk = (f & 3) << 2;       // k offset 0,4,8,12
            float4 av = *(const float4*)(Abase + r * DDIM + k0 + kk);
            As[kk + 0][r] = av.x; As[kk + 1][r] = av.y;
            As[kk + 2][r] = av.z; As[kk + 3][r] = av.w;
            float4 bv = *(const float4*)(Bbase + r * DDIM + k0 + kk);
            Bs[kk + 0][r] = bv.x; Bs[kk + 1][r] = bv.y;
            Bs[kk + 2][r] = bv.z; Bs[kk + 3][r] = bv.w;
        }
        __syncthreads();

        #pragma unroll
        for (int k = 0; k < BK; k++) {
            float a[TM], b[TN];
            *(float4*)&a[0] = *(const float4*)&As[k][m0];
            *(float4*)&a[4] = *(const float4*)&As[k][m0 + 4];
            *(float4*)&b[0] = *(const float4*)&Bs[k][n0];
            *(float4*)&b[4] = *(const float4*)&Bs[k][n0 + 4];
            #pragma unroll
            for (int i = 0; i < TM; i++)
                #pragma unroll
                for (int j = 0; j < TN; j++)
                    acc[i][j] = fmaf(a[i], b[j], acc[i][j]);
        }
        __syncthreads();
    }

    // ---- epilogue ----
    int rbase = bi * BM + m0;
    int cbase = bj * BM + n0;

    float sr[TM], mr[TM], ivr[TM]; int lr[TM];
    float sc[TN], mc[TN], ivc[TN]; int lc[TN];
    #pragma unroll
    for (int i = 0; i < TM; i++) {
        sr[i] = g_s[rbase + i]; mr[i] = g_m[rbase + i];
        ivr[i] = g_iv[rbase + i]; lr[i] = g_lab[rbase + i];
    }
    #pragma unroll
    for (int j = 0; j < TN; j++) {
        sc[j] = g_s[cbase + j]; mc[j] = g_m[cbase + j];
        ivc[j] = g_iv[cbase + j]; lc[j] = g_lab[cbase + j];
    }

    float psum = 0.0f, nsum = 0.0f;
    int pcnt = 0, ncnt = 0;
    bool offdiag = (bi != bj);

    #pragma unroll
    for (int i = 0; i < TM; i++) {
        #pragma unroll
        for (int j = 0; j < TN; j++) {
            int r = rbase + i;
            int c = cbase + j;
            float g = acc[i][j] * (1.0f / DDIM);
            float dm = mr[i] - mc[j];
            float num = sr[i] + sc[j] - 2.0f * g - dm * dm;
            if (r != c) {
                bool same = (lr[i] == lc[j]);
                float d1 = num * ivr[i];
                if (same) {
                    float p = d1 - POS_MARGIN;
                    if (p > 0.0f) { psum += p; pcnt++; }
                } else {
                    float q = NEG_MARGIN - d1;
                    if (q > 0.0f) { nsum += q; ncnt++; }
                }
                if (offdiag) {
                    float d2 = num * ivc[j];
                    if (same) {
                        float p = d2 - POS_MARGIN;
                        if (p > 0.0f) { psum += p; pcnt++; }
                    } else {
                        float q = NEG_MARGIN - d2;
                        if (q > 0.0f) { nsum += q; ncnt++; }
                    }
                }
            }
        }
    }

    psum = warpSumF(psum);
    nsum = warpSumF(nsum);
    pcnt = warpSumI(pcnt);
    ncnt = warpSumI(ncnt);
    if ((tid & 31) == 0) {
        atomicAdd(&g_acc[0], (double)psum);
        atomicAdd(&g_acc[1], (double)pcnt);
        atomicAdd(&g_acc[2], (double)nsum);
        atomicAdd(&g_acc[3], (double)ncnt);
    }
}

// ---------------------------------------------------------------------------
// Kernel 3: finalize
// ---------------------------------------------------------------------------
__global__ void k_fin(float* __restrict__ out) {
    double pos = g_acc[0] / (g_acc[1] + 1e-12);
    double neg = g_acc[2] / (g_acc[3] + 1e-12);
    double reg = (g_acc[4] / (double)NROWS) * 0.1;
    out[0] = (float)(pos + neg + reg);
}

extern "C" void kernel_launch(void* const* d_in, const int* in_sizes, int n_in,
                              void* d_out, int out_size) {
    const float* embeds = (const float*)d_in[0];
    const int*   lab32  = (const int*)d_in[1];   // int32 view; dtype detected at runtime
    float* out = (float*)d_out;
    (void)in_sizes; (void)n_in; (void)out_size;

    k_init<<<1, 256>>>(lab32);
    k_prep<<<NROWS, 256>>>(embeds, lab32);
    dim3 grid(NROWS / BN, NROWS / BM);
    k_main<<<grid, 256>>>();
    k_fin<<<1, 1>>>(out);
}

// round 2
// speedup vs baseline: 2.4701x; 2.4701x over previous
#include <cuda_runtime.h>

// SNRContrastiveLoss: N=8192, D=256, NUM_CLASSES=512
// loss = pos_sum/pos_cnt + neg_sum/neg_cnt + 0.1*mean(|row_sum(e)|)
// distmat_ij = (s_i + s_j - 2*g_ij - (m_i-m_j)^2) / (s_i - m_i^2)   (corr cancels)
// Round 2: TF32 tensor-core MMA for the N x N Gram matrix (fp32 FFMA path was
// at 89% of fp32 peak; tensor pipe is the only headroom).

#define NROWS 8192
#define DDIM  256
#define BM 128
#define BN 128
#define BK 32

#define POS_MARGIN 0.01f
#define NEG_MARGIN 0.2f

__device__ unsigned g_e[NROWS * DDIM];  // tf32-rounded normalized embeddings (8 MB)
__device__ float  g_s[NROWS];
__device__ float  g_m[NROWS];
__device__ float  g_iv[NROWS];
__device__ int    g_lab[NROWS];
__device__ double g_acc[5];             // pos_sum, pos_cnt, neg_sum, neg_cnt, reg_sum
__device__ int    g_is64;

__device__ __forceinline__ float warpSumF(float v) {
    #pragma unroll
    for (int o = 16; o > 0; o >>= 1) v += __shfl_xor_sync(0xffffffffu, v, o);
    return v;
}

// ---------------------------------------------------------------------------
// Kernel 0: zero accumulators + detect int64 vs int32 labels (odd words all 0).
// ---------------------------------------------------------------------------
__global__ void k_init(const int* __restrict__ lab32) {
    __shared__ int nz;
    int t = threadIdx.x;
    if (t == 0) nz = 0;
    __syncthreads();
    int loc = 0;
    for (int i = 2 * t + 1; i < NROWS; i += 2 * blockDim.x) loc |= lab32[i];
    if (loc) atomicOr(&nz, 1);
    __syncthreads();
    if (t == 0) {
        g_is64 = (nz == 0) ? 1 : 0;
        #pragma unroll
        for (int j = 0; j < 5; j++) g_acc[j] = 0.0;
    }
}

// ---------------------------------------------------------------------------
// Kernel 1: per-row normalize + stats. One block (256 threads) per row.
// Stores tf32-rounded (cvt.rna) bits for the MMA kernel.
// ---------------------------------------------------------------------------
__global__ __launch_bounds__(256) void k_prep(const float* __restrict__ x,
                                              const int* __restrict__ lab32) {
    int row = blockIdx.x;
    int t = threadIdx.x;
    float v = x[row * DDIM + t];

    __shared__ float sh[8];
    float s2 = warpSumF(v * v);
    if ((t & 31) == 0) sh[t >> 5] = s2;
    __syncthreads();
    if (t < 32) {
        float z = (t < 8) ? sh[t] : 0.0f;
        z = warpSumF(z);
        if (t == 0) sh[0] = z;
    }
    __syncthreads();
    float rinv = rsqrtf(sh[0]);
    float e = v * rinv;
    unsigned u;
    asm("cvt.rna.tf32.f32 %0, %1;" : "=r"(u) : "f"(e));
    g_e[row * DDIM + t] = u;
    __syncthreads();

    __shared__ float she[8], she2[8];
    float re = warpSumF(e);
    float re2 = warpSumF(e * e);
    if ((t & 31) == 0) { she[t >> 5] = re; she2[t >> 5] = re2; }
    __syncthreads();
    if (t == 0) {
        float se = 0.0f, se2 = 0.0f;
        #pragma unroll
        for (int i = 0; i < 8; i++) { se += she[i]; se2 += she2[i]; }
        float m = se * (1.0f / DDIM);
        float s = se2 * (1.0f / DDIM);
        g_s[row] = s;
        g_m[row] = m;
        g_iv[row] = 1.0f / (s - m * m);
        g_lab[row] = g_is64 ? lab32[2 * row] : lab32[row];
        atomicAdd(&g_acc[4], (double)fabsf(se));
    }
}

// ---------------------------------------------------------------------------
// Kernel 2: tf32 MMA pairwise tile kernel. Upper-triangular block tiles only;
// off-diagonal tiles apply the epilogue in both orientations.
// 8 warps (2 x 4), each computing a 64x32 warp tile = 4x4 m16n8k8 mma tiles.
// ---------------------------------------------------------------------------
__global__ __launch_bounds__(256) void k_main() {
    int bi = blockIdx.y;
    int bj = blockIdx.x;
    if (bj < bi) return;

    __shared__ unsigned As[BM][BK + 4];   // stride 36: conflict-free frag loads
    __shared__ unsigned Bs[BN][BK + 4];

    int tid = threadIdx.x;
    int warp = tid >> 5;
    int lane = tid & 31;
    int qr = lane >> 2;   // groupID 0..7
    int qc = lane & 3;    // threadID_in_group 0..3
    int wm = (warp & 1) * 64;   // warp M offset
    int wn = (warp >> 1) * 32;  // warp N offset

    const unsigned* Ab = g_e + (size_t)bi * BM * DDIM;
    const unsigned* Bb = g_e + (size_t)bj * BM * DDIM;

    float c[4][4][4];
    #pragma unroll
    for (int mi = 0; mi < 4; mi++)
        #pragma unroll
        for (int ni = 0; ni < 4; ni++)
            #pragma unroll
            for (int h = 0; h < 4; h++) c[mi][ni][h] = 0.0f;

    for (int k0 = 0; k0 < DDIM; k0 += BK) {
        // load 128x32 word tiles: 1024 uint4 slots per tile, 4 per thread
        #pragma unroll
        for (int l = 0; l < 4; l++) {
            int f = tid + l * 256;      // 0..1023
            int r = f >> 3;             // row 0..127
            int c4 = (f & 7) << 2;      // word col 0,4,..,28
            uint4 av = *(const uint4*)(Ab + (size_t)r * DDIM + k0 + c4);
            *(uint4*)&As[r][c4] = av;
            uint4 bv = *(const uint4*)(Bb + (size_t)r * DDIM + k0 + c4);
            *(uint4*)&Bs[r][c4] = bv;
        }
        __syncthreads();

        #pragma unroll
        for (int kk = 0; kk < BK; kk += 8) {
            unsigned a[4][4], b[4][2];
            #pragma unroll
            for (int mi = 0; mi < 4; mi++) {
                int r0 = wm + mi * 16 + qr;
                a[mi][0] = As[r0][kk + qc];
                a[mi][1] = As[r0 + 8][kk + qc];
                a[mi][2] = As[r0][kk + qc + 4];
                a[mi][3] = As[r0 + 8][kk + qc + 4];
            }
            #pragma unroll
            for (int ni = 0; ni < 4; ni++) {
                int r0 = wn + ni * 8 + qr;
                b[ni][0] = Bs[r0][kk + qc];
                b[ni][1] = Bs[r0][kk + qc + 4];
            }
            #pragma unroll
            for (int mi = 0; mi < 4; mi++)
                #pragma unroll
                for (int ni = 0; ni < 4; ni++)
                    asm volatile(
                        "mma.sync.aligned.m16n8k8.row.col.f32.tf32.tf32.f32 "
                        "{%0,%1,%2,%3}, {%4,%5,%6,%7}, {%8,%9}, {%0,%1,%2,%3};"
                        : "+f"(c[mi][ni][0]), "+f"(c[mi][ni][1]),
                          "+f"(c[mi][ni][2]), "+f"(c[mi][ni][3])
                        : "r"(a[mi][0]), "r"(a[mi][1]), "r"(a[mi][2]), "r"(a[mi][3]),
                          "r"(b[ni][0]), "r"(b[ni][1]));
        }
        __syncthreads();
    }

    // ---- epilogue ----
    // C frag layout: c0:(qr, 2qc) c1:(qr, 2qc+1) c2:(qr+8, 2qc) c3:(qr+8, 2qc+1)
    float sr[8], mr[8], ivr[8]; int lr[8];
    float sc[8], mc[8], ivc[8]; int lc[8];
    #pragma unroll
    for (int mi = 0; mi < 4; mi++) {
        int r = bi * BM + wm + mi * 16 + qr;
        sr[2*mi] = g_s[r];     mr[2*mi] = g_m[r];
        ivr[2*mi] = g_iv[r];   lr[2*mi] = g_lab[r];
        sr[2*mi+1] = g_s[r+8]; mr[2*mi+1] = g_m[r+8];
        ivr[2*mi+1] = g_iv[r+8]; lr[2*mi+1] = g_lab[r+8];
    }
    #pragma unroll
    for (int ni = 0; ni < 4; ni++) {
        int cix = bj * BN + wn + ni * 8 + 2 * qc;
        sc[2*ni] = g_s[cix];     mc[2*ni] = g_m[cix];
        ivc[2*ni] = g_iv[cix];   lc[2*ni] = g_lab[cix];
        sc[2*ni+1] = g_s[cix+1]; mc[2*ni+1] = g_m[cix+1];
        ivc[2*ni+1] = g_iv[cix+1]; lc[2*ni+1] = g_lab[cix+1];
    }

    float psum = 0.0f, nsum = 0.0f;
    float pcnt = 0.0f, ncnt = 0.0f;
    bool offdiag = (bi != bj);

    #pragma unroll
    for (int mi = 0; mi < 4; mi++) {
        #pragma unroll
        for (int ni = 0; ni < 4; ni++) {
            #pragma unroll
            for (int h = 0; h < 4; h++) {
                int ri = 2 * mi + (h >> 1);
                int ci = 2 * ni + (h & 1);
                int r = bi * BM + wm + mi * 16 + qr + (h >> 1) * 8;
                int cg = bj * BN + wn + ni * 8 + 2 * qc + (h & 1);
                if (r == cg) continue;
                float g = c[mi][ni][h] * (1.0f / DDIM);
                float dm = mr[ri] - mc[ci];
                float num = sr[ri] + sc[ci] - 2.0f * g - dm * dm;
                bool same = (lr[ri] == lc[ci]);
                float d1 = num * ivr[ri];
                if (same) {
                    float p = d1 - POS_MARGIN;
                    if (p > 0.0f) { psum += p; pcnt += 1.0f; }
                } else {
                    float q = NEG_MARGIN - d1;
                    if (q > 0.0f) { nsum += q; ncnt += 1.0f; }
                }
                if (offdiag) {
                    float d2 = num * ivc[ci];
                    if (same) {
                        float p = d2 - POS_MARGIN;
                        if (p > 0.0f) { psum += p; pcnt += 1.0f; }
                    } else {
                        float q = NEG_MARGIN - d2;
                        if (q > 0.0f) { nsum += q; ncnt += 1.0f; }
                    }
                }
            }
        }
    }

    // warp reduce, then block reduce in smem, single atomic set per block
    psum = warpSumF(psum);
    nsum = warpSumF(nsum);
    pcnt = warpSumF(pcnt);
    ncnt = warpSumF(ncnt);

    __shared__ float red[4][8];
    if (lane == 0) {
        red[0][warp] = psum; red[1][warp] = pcnt;
        red[2][warp] = nsum; red[3][warp] = ncnt;
    }
    __syncthreads();
    if (tid < 4) {
        float s = 0.0f;
        #pragma unroll
        for (int w = 0; w < 8; w++) s += red[tid][w];
        atomicAdd(&g_acc[tid], (double)s);
    }
}

// ---------------------------------------------------------------------------
// Kernel 3: finalize
// ---------------------------------------------------------------------------
__global__ void k_fin(float* __restrict__ out) {
    double pos = g_acc[0] / (g_acc[1] + 1e-12);
    double neg = g_acc[2] / (g_acc[3] + 1e-12);
    double reg = (g_acc[4] / (double)NROWS) * 0.1;
    out[0] = (float)(pos + neg + reg);
}

extern "C" void kernel_launch(void* const* d_in, const int* in_sizes, int n_in,
                              void* d_out, int out_size) {
    const float* embeds = (const float*)d_in[0];
    const int*   lab32  = (const int*)d_in[1];   // dtype detected at runtime
    float* out = (float*)d_out;
    (void)in_sizes; (void)n_in; (void)out_size;

    k_init<<<1, 256>>>(lab32);
    k_prep<<<NROWS, 256>>>(embeds, lab32);
    dim3 grid(NROWS / BN, NROWS / BM);
    k_main<<<grid, 256>>>();
    k_fin<<<1, 1>>>(out);
}

// round 10
// speedup vs baseline: 5.5068x; 2.2294x over previous
#include <cuda_runtime.h>
#include <cuda_fp16.h>
#include <cstdint>

// SNRContrastiveLoss: N=8192, D=256, NUM_CLASSES=512
// Round 7: fp16 mma.sync m16n8k16 + ldmatrix + cp.async double-buffer.
// (tcgen05 is unusable: harness PTX target is compute_103, no 'a' feature.)
// distmat_ij = (s_i + s_j - 2*g_ij - (m_i-m_j)^2) / (s_i - m_i^2)   (corr cancels)

#define NROWS 8192
#define DDIM  256
#define POS_MARGIN 0.01f
#define NEG_MARGIN 0.2f

#define BMN 128
#define BK  64                      // halves per stage (128 B rows)
#define NSTG (DDIM / BK)            // 4
#define TILE_BYTES (BMN * BK * 2)   // 16 KB
#define STAGE_BYTES (2 * TILE_BYTES)// A+B = 32 KB
#define DYN_SMEM (2 * STAGE_BYTES)  // 64 KB double buffer

__device__ __half g_eh[NROWS * DDIM];  // fp16 normalized embeddings (4 MB)
__device__ float  g_s[NROWS];
__device__ float  g_m[NROWS];
__device__ float  g_iv[NROWS];
__device__ int    g_lab[NROWS];
__device__ double g_acc[5];            // pos_sum, pos_cnt, neg_sum, neg_cnt, reg_sum
__device__ int    g_is64;

// ---------------- helpers ----------------
__device__ __forceinline__ uint32_t smem_u32(const void* p) {
    uint32_t a;
    asm("{ .reg .u64 t; cvta.to.shared.u64 t, %1; cvt.u32.u64 %0, t; }" : "=r"(a) : "l"(p));
    return a;
}
__device__ __forceinline__ void cp_async16(uint32_t dst, const void* src) {
    asm volatile("cp.async.cg.shared.global [%0], [%1], 16;" ::
                 "r"(dst), "l"(__cvta_generic_to_global(src)) : "memory");
}
__device__ __forceinline__ void cp_commit() {
    asm volatile("cp.async.commit_group;" ::: "memory");
}
template <int N>
__device__ __forceinline__ void cp_wait() {
    asm volatile("cp.async.wait_group %0;" :: "n"(N) : "memory");
}
__device__ __forceinline__ void ldsm_x4(uint32_t* r, uint32_t addr) {
    asm volatile("ldmatrix.sync.aligned.m8n8.x4.shared.b16 {%0,%1,%2,%3}, [%4];"
                 : "=r"(r[0]), "=r"(r[1]), "=r"(r[2]), "=r"(r[3]) : "r"(addr));
}
__device__ __forceinline__ void mma_f16(float* c, const uint32_t* a, uint32_t b0, uint32_t b1) {
    asm volatile(
        "mma.sync.aligned.m16n8k16.row.col.f32.f16.f16.f32 "
        "{%0,%1,%2,%3}, {%4,%5,%6,%7}, {%8,%9}, {%0,%1,%2,%3};"
        : "+f"(c[0]), "+f"(c[1]), "+f"(c[2]), "+f"(c[3])
        : "r"(a[0]), "r"(a[1]), "r"(a[2]), "r"(a[3]), "r"(b0), "r"(b1));
}
__device__ __forceinline__ float warpSumF(float v) {
    #pragma unroll
    for (int o = 16; o > 0; o >>= 1) v += __shfl_xor_sync(0xffffffffu, v, o);
    return v;
}

// ---------------------------------------------------------------------------
// Kernel 0: zero accumulators + detect int64 vs int32 labels (odd words all 0).
// ---------------------------------------------------------------------------
__global__ void k_init(const int* __restrict__ lab32) {
    __shared__ int nz;
    int t = threadIdx.x;
    if (t == 0) nz = 0;
    __syncthreads();
    int loc = 0;
    for (int i = 2 * t + 1; i < NROWS; i += 2 * blockDim.x) loc |= lab32[i];
    if (loc) atomicOr(&nz, 1);
    __syncthreads();
    if (t == 0) {
        g_is64 = (nz == 0) ? 1 : 0;
        #pragma unroll
        for (int j = 0; j < 5; j++) g_acc[j] = 0.0;
    }
}

// ---------------------------------------------------------------------------
// Kernel 1: per-row normalize + stats, fp16 store.
// ---------------------------------------------------------------------------
__global__ __launch_bounds__(256) void k_prep(const float* __restrict__ x,
                                              const int* __restrict__ lab32) {
    int row = blockIdx.x;
    int t = threadIdx.x;
    float v = x[row * DDIM + t];

    __shared__ float sh[8];
    float s2 = warpSumF(v * v);
    if ((t & 31) == 0) sh[t >> 5] = s2;
    __syncthreads();
    if (t < 32) {
        float z = (t < 8) ? sh[t] : 0.0f;
        z = warpSumF(z);
        if (t == 0) sh[0] = z;
    }
    __syncthreads();
    float rinv = rsqrtf(sh[0]);
    float e = v * rinv;
    g_eh[row * DDIM + t] = __float2half_rn(e);
    __syncthreads();

    __shared__ float she[8], she2[8];
    float re = warpSumF(e);
    float re2 = warpSumF(e * e);
    if ((t & 31) == 0) { she[t >> 5] = re; she2[t >> 5] = re2; }
    __syncthreads();
    if (t == 0) {
        float se = 0.0f, se2 = 0.0f;
        #pragma unroll
        for (int i = 0; i < 8; i++) { se += she[i]; se2 += she2[i]; }
        float m = se * (1.0f / DDIM);
        float s = se2 * (1.0f / DDIM);
        g_s[row] = s;
        g_m[row] = m;
        g_iv[row] = 1.0f / (s - m * m);
        g_lab[row] = g_is64 ? lab32[2 * row] : lab32[row];
        atomicAdd(&g_acc[4], (double)fabsf(se));
    }
}

// ---------------------------------------------------------------------------
// Kernel 2: fp16 mma.sync 128x128 tile kernel, upper-triangular tiles.
// 8 warps 2x4; warp tile 64x32 = 4x4 m16n8k16 tiles; BK=64 double-buffered.
// ---------------------------------------------------------------------------
extern __shared__ char dynsmem[];

__device__ __forceinline__ void load_stage(uint32_t abuf, uint32_t bbuf,
                                           const __half* Ab, const __half* Bb,
                                           int k0, int tid) {
    #pragma unroll
    for (int l = 0; l < 4; l++) {
        int f = tid + l * 256;          // 0..1023 chunk id of one 16KB tile
        int r = f >> 3;                 // row 0..127
        int c = f & 7;                  // 16B chunk within 128B row
        uint32_t sw = (uint32_t)(r * 128 + ((c ^ (r & 7)) << 4));
        cp_async16(abuf + sw, Ab + (size_t)r * DDIM + k0 + c * 8);
        cp_async16(bbuf + sw, Bb + (size_t)r * DDIM + k0 + c * 8);
    }
    cp_commit();
}

// address of the 8x8 b16 matrix row for ldmatrix.x4 (A and B share the pattern)
__device__ __forceinline__ uint32_t frag_addr(uint32_t tbuf, int base_row, int kc, int lane) {
    int row = base_row + ((lane >> 3) & 1) * 8 + (lane & 7);
    int chunk = kc + (lane >> 4);
    return tbuf + (uint32_t)(row * 128 + ((chunk ^ (row & 7)) << 4));
}

__global__ __launch_bounds__(256, 2) void k_main() {
    int bi = blockIdx.y;
    int bj = blockIdx.x;
    if (bj < bi) return;

    int tid = threadIdx.x;
    int warp = tid >> 5;
    int lane = tid & 31;
    int qr = lane >> 2;
    int qc = lane & 3;
    int wm = (warp & 1) * 64;
    int wn = (warp >> 1) * 32;

    uint32_t sbase = smem_u32(dynsmem);
    const __half* Ab = g_eh + (size_t)bi * BMN * DDIM;
    const __half* Bb = g_eh + (size_t)bj * BMN * DDIM;

    float c[4][4][4];
    #pragma unroll
    for (int mi = 0; mi < 4; mi++)
        #pragma unroll
        for (int ni = 0; ni < 4; ni++)
            #pragma unroll
            for (int h = 0; h < 4; h++) c[mi][ni][h] = 0.0f;

    // prologue: fill both stages
    load_stage(sbase, sbase + TILE_BYTES, Ab, Bb, 0, tid);
    load_stage(sbase + STAGE_BYTES, sbase + STAGE_BYTES + TILE_BYTES, Ab, Bb, BK, tid);

    #pragma unroll
    for (int k = 0; k < NSTG; k++) {
        if (k < NSTG - 1) cp_wait<1>(); else cp_wait<0>();
        __syncthreads();

        uint32_t abuf = sbase + (uint32_t)(k & 1) * STAGE_BYTES;
        uint32_t bbuf = abuf + TILE_BYTES;

        #pragma unroll
        for (int kt = 0; kt < BK / 16; kt++) {        // 4 k-subtiles of 16
            int kc = kt * 2;
            uint32_t a[4][4], b[2][4];
            #pragma unroll
            for (int mi = 0; mi < 4; mi++)
                ldsm_x4(a[mi], frag_addr(abuf, wm + mi * 16, kc, lane));
            #pragma unroll
            for (int nj = 0; nj < 2; nj++)
                ldsm_x4(b[nj], frag_addr(bbuf, wn + nj * 16, kc, lane));
            #pragma unroll
            for (int mi = 0; mi < 4; mi++)
                #pragma unroll
                for (int ni = 0; ni < 4; ni++) {
                    int nj = ni >> 1, sel = ni & 1;
                    mma_f16(c[mi][ni], a[mi], b[nj][sel], b[nj][sel + 2]);
                }
        }

        if (k + 2 < NSTG) {
            __syncthreads();   // all warps done reading buf (k&1) before refill
            uint32_t nab = sbase + (uint32_t)(k & 1) * STAGE_BYTES;
            load_stage(nab, nab + TILE_BYTES, Ab, Bb, (k + 2) * BK, tid);
        }
    }

    // ---- epilogue ----
    // C frag: c0:(qr,2qc) c1:(qr,2qc+1) c2:(qr+8,2qc) c3:(qr+8,2qc+1)
    int rbase = bi * BMN + wm;
    int cbase = bj * BMN + wn;

    float sr[8], mr[8], ivr[8]; int lr[8];
    float sc[8], mc[8], ivc[8]; int lc[8];
    #pragma unroll
    for (int mi = 0; mi < 4; mi++) {
        int r = rbase + mi * 16 + qr;
        sr[2*mi]   = g_s[r];   mr[2*mi]   = g_m[r];
        ivr[2*mi]  = g_iv[r];  lr[2*mi]   = g_lab[r];
        sr[2*mi+1] = g_s[r+8]; mr[2*mi+1] = g_m[r+8];
        ivr[2*mi+1]= g_iv[r+8];lr[2*mi+1] = g_lab[r+8];
    }
    #pragma unroll
    for (int ni = 0; ni < 4; ni++) {
        int cix = cbase + ni * 8 + 2 * qc;
        sc[2*ni]   = g_s[cix];   mc[2*ni]   = g_m[cix];
        ivc[2*ni]  = g_iv[cix];  lc[2*ni]   = g_lab[cix];
        sc[2*ni+1] = g_s[cix+1]; mc[2*ni+1] = g_m[cix+1];
        ivc[2*ni+1]= g_iv[cix+1];lc[2*ni+1] = g_lab[cix+1];
    }

    float psum = 0.0f, nsum = 0.0f, pcnt = 0.0f, ncnt = 0.0f;
    bool offdiag = (bi != bj);

    #pragma unroll
    for (int mi = 0; mi < 4; mi++) {
        #pragma unroll
        for (int ni = 0; ni < 4; ni++) {
            #pragma unroll
            for (int h = 0; h < 4; h++) {
                int ri = 2 * mi + (h >> 1);
                int ci = 2 * ni + (h & 1);
                int r  = rbase + mi * 16 + qr + (h >> 1) * 8;
                int cg = cbase + ni * 8 + 2 * qc + (h & 1);
                if (r == cg) continue;
                float g = c[mi][ni][h] * (1.0f / DDIM);
                float dm = mr[ri] - mc[ci];
                float num = sr[ri] + sc[ci] - 2.0f * g - dm * dm;
                bool same = (lr[ri] == lc[ci]);
                float d1 = num * ivr[ri];
                if (same) {
                    float p = d1 - POS_MARGIN;
                    if (p > 0.0f) { psum += p; pcnt += 1.0f; }
                } else {
                    float q = NEG_MARGIN - d1;
                    if (q > 0.0f) { nsum += q; ncnt += 1.0f; }
                }
                if (offdiag) {
                    float d2 = num * ivc[ci];
                    if (same) {
                        float p = d2 - POS_MARGIN;
                        if (p > 0.0f) { psum += p; pcnt += 1.0f; }
                    } else {
                        float q = NEG_MARGIN - d2;
                        if (q > 0.0f) { nsum += q; ncnt += 1.0f; }
                    }
                }
            }
        }
    }

    psum = warpSumF(psum); nsum = warpSumF(nsum);
    pcnt = warpSumF(pcnt); ncnt = warpSumF(ncnt);

    __shared__ float red[4][8];
    if (lane == 0) {
        red[0][warp] = psum; red[1][warp] = pcnt;
        red[2][warp] = nsum; red[3][warp] = ncnt;
    }
    __syncthreads();
    if (tid < 4) {
        float s = 0.0f;
        #pragma unroll
        for (int w = 0; w < 8; w++) s += red[tid][w];
        atomicAdd(&g_acc[tid], (double)s);
    }
}

// ---------------------------------------------------------------------------
// Kernel 3: finalize
// ---------------------------------------------------------------------------
__global__ void k_fin(float* __restrict__ out) {
    double pos = g_acc[0] / (g_acc[1] + 1e-12);
    double neg = g_acc[2] / (g_acc[3] + 1e-12);
    double reg = (g_acc[4] / (double)NROWS) * 0.1;
    out[0] = (float)(pos + neg + reg);
}

extern "C" void kernel_launch(void* const* d_in, const int* in_sizes, int n_in,
                              void* d_out, int out_size) {
    const float* embeds = (const float*)d_in[0];
    const int*   lab32  = (const int*)d_in[1];   // dtype detected at runtime
    float* out = (float*)d_out;
    (void)in_sizes; (void)n_in; (void)out_size;

    cudaFuncSetAttribute(k_main, cudaFuncAttributeMaxDynamicSharedMemorySize, DYN_SMEM);

    k_init<<<1, 256>>>(lab32);
    k_prep<<<NROWS, 256>>>(embeds, lab32);
    dim3 grid(NROWS / BMN, NROWS / BMN);
    k_main<<<grid, 256, DYN_SMEM>>>();
    k_fin<<<1, 1>>>(out);
}